// round 1
// baseline (speedup 1.0000x reference)
#include <cuda_runtime.h>

#define KC 100
#define DD 64

// Scratch (no allocations allowed): accumulators + detection flag.
__device__ float g_sum[KC * DD];   // raw segment sum S_k
__device__ float g_sumsq[KC];      // Q_k = sum ||x||^2
__device__ float g_cnt[KC];        // n_k (assigned count)
__device__ float g_rowmax[KC];     // per-row max of Rij
__device__ int   g_is64;           // clustering dtype: 1 = int64, 0 = int32

// ---------------------------------------------------------------------------
// Kernel 0: zero accumulators + detect label element width.
// If labels are int64 (values 0..99), every odd int32 word is 0.
// ---------------------------------------------------------------------------
__global__ void k_init(const void* __restrict__ cl, int n) {
    __shared__ int s_nonzero;
    if (threadIdx.x == 0) s_nonzero = 0;
    __syncthreads();

    for (int i = threadIdx.x; i < KC * DD; i += blockDim.x) g_sum[i] = 0.0f;
    if (threadIdx.x < KC) {
        g_sumsq[threadIdx.x] = 0.0f;
        g_cnt[threadIdx.x]   = 0.0f;
    }

    const int* ci  = (const int*)cl;
    int        lim = min(1024, n / 2);
    int        bad = 0;
    for (int i = threadIdx.x; i < lim; i += blockDim.x)
        if (ci[2 * i + 1] != 0) bad = 1;
    if (bad) atomicOr(&s_nonzero, 1);
    __syncthreads();
    if (threadIdx.x == 0) g_is64 = (s_nonzero == 0) ? 1 : 0;
}

// ---------------------------------------------------------------------------
// Kernel 1: fused single pass. Per warp: 32 consecutive points per iteration.
// Shared-memory accumulation (conflict-free banks), then global atomic flush.
// ---------------------------------------------------------------------------
__global__ __launch_bounds__(512) void k_accum(const float* __restrict__ data,
                                               const void* __restrict__ cl,
                                               int n) {
    __shared__ float s_sum[KC * DD];  // 25.6 KB
    __shared__ float s_sq[KC];
    __shared__ float s_c[KC];

    for (int i = threadIdx.x; i < KC * DD; i += blockDim.x) s_sum[i] = 0.0f;
    for (int i = threadIdx.x; i < KC; i += blockDim.x) { s_sq[i] = 0.0f; s_c[i] = 0.0f; }
    __syncthreads();

    const int is64  = g_is64;
    const int lane  = threadIdx.x & 31;
    const int warp  = (blockIdx.x * blockDim.x + threadIdx.x) >> 5;
    const int nwarp = (gridDim.x * blockDim.x) >> 5;

    const long long stride = (long long)nwarp * 32;
    for (long long base = (long long)warp * 32; base < n; base += stride) {
        int cnt = min(32, (int)(n - base));
        int myc = 0;
        if (lane < cnt) {
            myc = is64 ? (int)((const long long*)cl)[base + lane]
                       : ((const int*)cl)[base + lane];
        }
        for (int k = 0; k < cnt; k++) {
            int          c   = __shfl_sync(0xffffffffu, myc, k);
            const float* row = data + (base + k) * DD;
            float a = row[lane];        // coalesced 128B
            float b = row[lane + 32];   // coalesced 128B
            // conflict-free shared atomics: banks 0..31, twice
            atomicAdd(&s_sum[c * DD + lane], a);
            atomicAdd(&s_sum[c * DD + lane + 32], b);
            float sq = a * a + b * b;
#pragma unroll
            for (int o = 16; o; o >>= 1) sq += __shfl_xor_sync(0xffffffffu, sq, o);
            if (lane == 0) {
                atomicAdd(&s_sq[c], sq);
                atomicAdd(&s_c[c], 1.0f);
            }
        }
    }
    __syncthreads();

    for (int i = threadIdx.x; i < KC * DD; i += blockDim.x) atomicAdd(&g_sum[i], s_sum[i]);
    for (int i = threadIdx.x; i < KC; i += blockDim.x) {
        atomicAdd(&g_sumsq[i], s_sq[i]);
        atomicAdd(&g_cnt[i], s_c[i]);
    }
}

// ---------------------------------------------------------------------------
// Kernel 2: one block per cluster-row i. Recompute A, Si (tiny), then
// row-wise max of Rij = (Si + Sj) / ||Ai - Aj||.
// Shared A padded to 65 to keep j-indexed reads conflict-free.
// ---------------------------------------------------------------------------
__global__ __launch_bounds__(128) void k_rows() {
    __shared__ float s_A[KC * (DD + 1)];  // 26 KB
    __shared__ float s_Si[KC];
    __shared__ float s_red[4];

    // A_k = (S_k + 0.001) / (n_k + 1)
    for (int idx = threadIdx.x; idx < KC * DD; idx += blockDim.x) {
        int k = idx >> 6, d = idx & 63;
        s_A[k * 65 + d] = (g_sum[idx] + 0.001f) / (g_cnt[k] + 1.0f);
    }
    __syncthreads();

    // Si_k = sqrt((0.001 + Q_k - 2 A.S + n_k ||A||^2) / (n_k + 1))
    for (int k = threadIdx.x; k < KC; k += blockDim.x) {
        float nk = g_cnt[k];
        float dot = 0.0f, a2 = 0.0f;
#pragma unroll 8
        for (int d = 0; d < DD; d++) {
            float av = s_A[k * 65 + d];
            float sv = g_sum[k * DD + d];
            dot = fmaf(av, sv, dot);
            a2  = fmaf(av, av, a2);
        }
        float sqsum = g_sumsq[k] - 2.0f * dot + nk * a2;
        s_Si[k] = sqrtf((0.001f + sqsum) / (nk + 1.0f));
    }
    __syncthreads();

    const int i  = blockIdx.x;
    const float si = s_Si[i];
    float m = 0.0f;
    for (int j = threadIdx.x; j < KC; j += blockDim.x) {
        if (j == i) continue;
        float d2 = 0.0f;
#pragma unroll 8
        for (int d = 0; d < DD; d++) {
            float df = s_A[i * 65 + d] - s_A[j * 65 + d];
            d2 = fmaf(df, df, d2);
        }
        float r = (si + s_Si[j]) / sqrtf(d2);
        m = fmaxf(m, r);
    }
#pragma unroll
    for (int o = 16; o; o >>= 1) m = fmaxf(m, __shfl_xor_sync(0xffffffffu, m, o));
    if ((threadIdx.x & 31) == 0) s_red[threadIdx.x >> 5] = m;
    __syncthreads();
    if (threadIdx.x == 0)
        g_rowmax[i] = fmaxf(fmaxf(s_red[0], s_red[1]), fmaxf(s_red[2], s_red[3]));
}

// ---------------------------------------------------------------------------
// Kernel 3: deterministic final reduction -> scalar output.
// ---------------------------------------------------------------------------
__global__ void k_final(float* __restrict__ out) {
    if (threadIdx.x == 0) {
        float t = 0.0f;
        for (int k = 0; k < KC; k++) t += g_rowmax[k];
        out[0] = t / (float)KC;
    }
}

// ---------------------------------------------------------------------------
extern "C" void kernel_launch(void* const* d_in, const int* in_sizes, int n_in,
                              void* d_out, int out_size) {
    const float* data;
    const void*  cl;
    int          n;
    // robust to input ordering: data has 64x more elements than clustering
    if (in_sizes[0] >= in_sizes[1]) {
        data = (const float*)d_in[0];
        cl   = d_in[1];
        n    = in_sizes[1];
    } else {
        data = (const float*)d_in[1];
        cl   = d_in[0];
        n    = in_sizes[0];
    }

    k_init<<<1, 1024>>>(cl, n);
    k_accum<<<304, 512>>>(data, cl, n);
    k_rows<<<KC, 128>>>();
    k_final<<<1, 128>>>((float*)d_out);
}

// round 2
// speedup vs baseline: 1.3894x; 1.3894x over previous
#include <cuda_runtime.h>

#define KC  100
#define DD  64
#define TP  1024            // points per tile
#define CAP 352             // per-warp list capacity (mean 41, 54 sigma headroom)
#define WPB 25              // warps per block; warp w owns clusters [4w, 4w+4)
#define TPB (WPB * 32)      // 800 threads

// Scratch (static device globals — no allocations).
__device__ float g_sum[KC * DD];   // segment sums S_k
__device__ float g_sumsq[KC];      // Q_k = sum ||x||^2
__device__ float g_cnt[KC];        // assigned counts n_k
__device__ int   g_is64;           // label dtype: 1 = int64, 0 = int32

// ---------------------------------------------------------------------------
// Kernel 0: zero accumulators + detect label element width.
// If labels are int64 with values 0..99, every odd int32 word is 0.
// ---------------------------------------------------------------------------
__global__ void k_init(const void* __restrict__ cl, int n) {
    __shared__ int s_nz;
    if (threadIdx.x == 0) s_nz = 0;
    __syncthreads();

    for (int i = threadIdx.x; i < KC * DD; i += blockDim.x) g_sum[i] = 0.0f;
    if (threadIdx.x < KC) { g_sumsq[threadIdx.x] = 0.0f; g_cnt[threadIdx.x] = 0.0f; }

    const int* ci = (const int*)cl;
    int lim = min(1024, n / 2), bad = 0;
    for (int i = threadIdx.x; i < lim; i += blockDim.x)
        if (ci[2 * i + 1] != 0) bad = 1;
    if (bad) atomicOr(&s_nz, 1);
    __syncthreads();
    if (threadIdx.x == 0) g_is64 = (s_nz == 0) ? 1 : 0;
}

// ---------------------------------------------------------------------------
// Kernel 1: cluster-ownership accumulation. No shared/global atomics in the
// hot loop; register accumulators per warp, REDG flush once at the end.
// ---------------------------------------------------------------------------
__global__ __launch_bounds__(TPB) void k_accum(const float* __restrict__ data,
                                               const void* __restrict__ cl,
                                               int n) {
    __shared__ int s_list[WPB][CAP];   // warp-private compacted (idx<<8)|c

    const int lane  = threadIdx.x & 31;
    const int w     = threadIdx.x >> 5;
    const int cbase = w << 2;          // warp owns [cbase, cbase+4)
    const int is64  = g_is64;
    const long long* cl64 = (const long long*)cl;
    const int*       cl32 = (const int*)cl;

    float sa0=0,sa1=0,sa2=0,sa3=0;     // sum of dims [lane]
    float sb0=0,sb1=0,sb2=0,sb3=0;     // sum of dims [lane+32]
    float q0=0,q1=0,q2=0,q3=0;         // per-lane partial of Q
    float n0=0,n1=0,n2=0,n3=0;         // counts (identical across lanes)

#define ACC(e, a, b) do {                                                   \
    int   c_ = (e) & 255; int j_ = c_ & 3;                                  \
    float t_ = fmaf((a), (a), (b) * (b));                                   \
    if (j_ == 0) { sa0 += (a); sb0 += (b); q0 += t_; n0 += 1.0f; }          \
    if (j_ == 1) { sa1 += (a); sb1 += (b); q1 += t_; n1 += 1.0f; }          \
    if (j_ == 2) { sa2 += (a); sb2 += (b); q2 += t_; n2 += 1.0f; }          \
    if (j_ == 3) { sa3 += (a); sb3 += (b); q3 += t_; n3 += 1.0f; }          \
} while (0)

    const int ntiles = (n + TP - 1) / TP;
    for (int t = blockIdx.x; t < ntiles; t += gridDim.x) {
        const long long tb = (long long)t * TP;
        const int tn = min(TP, (int)((long long)n - tb));
        const float* tdata = data + tb * DD;

        // ---- Phase A: scan labels, compact matches into warp-private list
        int cnt = 0;
        for (int g = 0; g * 32 < tn; g++) {
            int idx = g * 32 + lane;
            int myc = 255;
            if (idx < tn)
                myc = is64 ? (int)__ldg(cl64 + tb + idx) : __ldg(cl32 + tb + idx);
            bool m = (myc >= cbase) && (myc < cbase + 4);
            unsigned mask = __ballot_sync(0xffffffffu, m);
            int gc = __popc(mask);
            if (cnt + gc <= CAP) {
                if (m)
                    s_list[w][cnt + __popc(mask & ((1u << lane) - 1u))] = (idx << 8) | myc;
                cnt += gc;
            } else {
                // overflow fallback: process this group collectively, now
                while (mask) {
                    int k = __ffs(mask) - 1; mask &= mask - 1;
                    int c = __shfl_sync(0xffffffffu, myc, k);
                    const float* r = tdata + (long long)(g * 32 + k) * DD;
                    float a = __ldcs(r + lane), b = __ldcs(r + lane + 32);
                    ACC(c, a, b);
                }
            }
        }
        __syncwarp();

        // ---- Phase B: batched row loads (MLP ~16) + register accumulate
        int i = 0;
        for (; i + 8 <= cnt; i += 8) {
            int e0 = s_list[w][i+0], e1 = s_list[w][i+1];
            int e2 = s_list[w][i+2], e3 = s_list[w][i+3];
            int e4 = s_list[w][i+4], e5 = s_list[w][i+5];
            int e6 = s_list[w][i+6], e7 = s_list[w][i+7];
            const float* r0 = tdata + (long long)(e0 >> 8) * DD;
            const float* r1 = tdata + (long long)(e1 >> 8) * DD;
            const float* r2 = tdata + (long long)(e2 >> 8) * DD;
            const float* r3 = tdata + (long long)(e3 >> 8) * DD;
            const float* r4 = tdata + (long long)(e4 >> 8) * DD;
            const float* r5 = tdata + (long long)(e5 >> 8) * DD;
            const float* r6 = tdata + (long long)(e6 >> 8) * DD;
            const float* r7 = tdata + (long long)(e7 >> 8) * DD;
            float a0 = __ldcs(r0 + lane), b0 = __ldcs(r0 + lane + 32);
            float a1 = __ldcs(r1 + lane), b1 = __ldcs(r1 + lane + 32);
            float a2 = __ldcs(r2 + lane), b2 = __ldcs(r2 + lane + 32);
            float a3 = __ldcs(r3 + lane), b3 = __ldcs(r3 + lane + 32);
            float a4 = __ldcs(r4 + lane), b4 = __ldcs(r4 + lane + 32);
            float a5 = __ldcs(r5 + lane), b5 = __ldcs(r5 + lane + 32);
            float a6 = __ldcs(r6 + lane), b6 = __ldcs(r6 + lane + 32);
            float a7 = __ldcs(r7 + lane), b7 = __ldcs(r7 + lane + 32);
            ACC(e0, a0, b0); ACC(e1, a1, b1); ACC(e2, a2, b2); ACC(e3, a3, b3);
            ACC(e4, a4, b4); ACC(e5, a5, b5); ACC(e6, a6, b6); ACC(e7, a7, b7);
        }
        for (; i < cnt; i++) {
            int e = s_list[w][i];
            const float* r = tdata + (long long)(e >> 8) * DD;
            float a = __ldcs(r + lane), b = __ldcs(r + lane + 32);
            ACC(e, a, b);
        }
        __syncwarp();
    }

    // ---- Flush: ~600 REDG total per block
    float sas[4] = {sa0, sa1, sa2, sa3};
    float sbs[4] = {sb0, sb1, sb2, sb3};
    float qs[4]  = {q0, q1, q2, q3};
    float ns[4]  = {n0, n1, n2, n3};
#pragma unroll
    for (int j = 0; j < 4; j++) {
        int c = cbase + j;
        atomicAdd(&g_sum[c * DD + lane],      sas[j]);
        atomicAdd(&g_sum[c * DD + lane + 32], sbs[j]);
        float qq = qs[j];
#pragma unroll
        for (int o = 16; o; o >>= 1) qq += __shfl_xor_sync(0xffffffffu, qq, o);
        if (lane == 0) {
            atomicAdd(&g_sumsq[c], qq);
            atomicAdd(&g_cnt[c],   ns[j]);
        }
    }
#undef ACC
}

// ---------------------------------------------------------------------------
// Kernel 2: fused epilogue, single block. A_k, Si_k (via Q - 2A.S + n||A||^2),
// row-wise max of Rij, final mean -> scalar.
// ---------------------------------------------------------------------------
__global__ __launch_bounds__(TPB) void k_epi(float* __restrict__ out) {
    __shared__ float s_A[KC * (DD + 1)];   // padded: conflict-free j-reads
    __shared__ float s_Si[KC];
    __shared__ float s_rm[KC];
    const int tid = threadIdx.x;

    for (int idx = tid; idx < KC * DD; idx += TPB) {
        int k = idx >> 6, d = idx & 63;
        s_A[k * 65 + d] = (g_sum[idx] + 0.001f) / (g_cnt[k] + 1.0f);
    }
    __syncthreads();

    for (int k = tid; k < KC; k += TPB) {
        float nk = g_cnt[k], dot = 0.0f, a2 = 0.0f;
#pragma unroll 8
        for (int d = 0; d < DD; d++) {
            float av = s_A[k * 65 + d], sv = g_sum[k * DD + d];
            dot = fmaf(av, sv, dot);
            a2  = fmaf(av, av, a2);
        }
        float ss = g_sumsq[k] - 2.0f * dot + nk * a2;
        s_Si[k] = sqrtf((0.001f + ss) / (nk + 1.0f));
    }
    __syncthreads();

    const int w = tid >> 5, lane = tid & 31;
    for (int r = w; r < KC; r += WPB) {
        float si = s_Si[r];
        float m = 0.0f;
        for (int j = lane; j < KC; j += 32) {
            if (j == r) continue;
            float d2 = 0.0f;
#pragma unroll 8
            for (int d = 0; d < DD; d++) {
                float df = s_A[r * 65 + d] - s_A[j * 65 + d];
                d2 = fmaf(df, df, d2);
            }
            m = fmaxf(m, (si + s_Si[j]) / sqrtf(d2));
        }
#pragma unroll
        for (int o = 16; o; o >>= 1) m = fmaxf(m, __shfl_xor_sync(0xffffffffu, m, o));
        if (lane == 0) s_rm[r] = m;
    }
    __syncthreads();
    if (tid == 0) {
        float tsum = 0.0f;
        for (int k = 0; k < KC; k++) tsum += s_rm[k];
        out[0] = tsum / (float)KC;
    }
}

// ---------------------------------------------------------------------------
extern "C" void kernel_launch(void* const* d_in, const int* in_sizes, int n_in,
                              void* d_out, int out_size) {
    const float* data;
    const void*  cl;
    int          n;
    if (in_sizes[0] >= in_sizes[1]) {
        data = (const float*)d_in[0]; cl = d_in[1]; n = in_sizes[1];
    } else {
        data = (const float*)d_in[1]; cl = d_in[0]; n = in_sizes[0];
    }

    k_init <<<1, 1024>>>(cl, n);
    k_accum<<<296, TPB>>>(data, cl, n);
    k_epi  <<<1, TPB>>>((float*)d_out);
}